// round 7
// baseline (speedup 1.0000x reference)
#include <cuda_runtime.h>
#include <math.h>

// Problem constants
#define HW      262144        // 512*512
#define NTILES  16384         // 2M pixels / 128-pixel tiles
#define GRID1   296           // 2 * 148 SMs
#define K       19
#define KC      1216          // 19*64

// Scratch (no allocation allowed -> __device__ globals)
__device__ float    g_psums[GRID1 * KC];
__device__ int      g_pcnts[K * GRID1];  // [class][block]
__device__ float    g_sums[KC];
__device__ unsigned g_done;              // zero-init; reset by last block each run

#define TILE_F   8192
// dyn smem: 2 tiles + order[2][128] + bstart/bcnt/bcur[2][19]
#define SMEM_BYTES (2*TILE_F*4 + 2*128*4 + 3*2*19*4 + 64)

// ---------------------------------------------------------------------------
// K1: streaming centroid scatter-sum, class-owned register accumulation,
// double-buffered single-barrier pipeline, float4-granular tile.
//   Tile: row = pixel (16 float4 slots), slot = w ^ (q&15); float4 holds
//   channels (w, 16+w, 32+w, 48+w). Loader: 4x STS.128 (conflict-free octets).
//   Class warp: lanes 0-15 process even bucket entries, 16-31 odd; per element
//   1x LDS.128 + 4 FADD; final shfl_xor(16) merge.
// ---------------------------------------------------------------------------
__global__ __launch_bounds__(640, 2) void k1_kernel(const float* __restrict__ inp,
                                                    const int* __restrict__ tgt32) {
    extern __shared__ float sm[];
    float* tiles  = sm;                        // [2][8192]
    int*   order  = (int*)(sm + 2 * TILE_F);   // [2][128]
    int*   bstart = order + 256;               // [2][19]
    int*   bcnt   = bstart + 38;               // [2][19]
    int*   bcur   = bcnt + 38;                 // [2][19]

    const int tid  = threadIdx.x;
    const int lane = tid & 31;
    const int wid  = tid >> 5;
    const int bid  = blockIdx.x;

    // loader mapping (tid < 512): q = pixel-quad, channels w,16+w,32+w,48+w
    const int q = tid & 31, w = (tid >> 5) & 15;
    const int c0 = w, c1 = 16 + w, c2 = 32 + w, c3 = 48 + w;
    const int slot = w ^ (q & 15);             // float4 slot within pixel row

    // accumulate mapping: half h (entry parity), channel group g
    const int h = lane >> 4, g = lane & 15;

    float r0 = 0.f, r1 = 0.f, r2 = 0.f, r3 = 0.f;
    int   ccnt = 0;
    float4 v0, v1, v2, v3;
    int   lab0 = 0, lab1 = 0, lab2 = 0, lab3 = 0;
    int   shift = 0;

    int t = bid, par = 0;

    // ---- prologue: prefetch tile bid (data + labels), detect targets dtype ----
    {
        const int b = t >> 11, hw0 = (t & 2047) << 7;
        if (tid < 512) {
            const float* p = inp + ((size_t)b << 24) + hw0 + (q << 2);
            v0 = __ldcs((const float4*)(p + (size_t)c0 * HW));
            v1 = __ldcs((const float4*)(p + (size_t)c1 * HW));
            v2 = __ldcs((const float4*)(p + (size_t)c2 * HW));
            v3 = __ldcs((const float4*)(p + (size_t)c3 * HW));
        }
        if (wid == 19) {
            // int64 labels 0..18 have all-zero high words; int32 ~never does
            if (lane == 0) {
                int all0 = 1;
                #pragma unroll
                for (int i = 0; i < 32; ++i)
                    if (tgt32[2 * i + 1] != 0) all0 = 0;
                shift = all0;
            }
            shift = __shfl_sync(0xffffffffu, shift, 0);
            const int tb = (b << 18) + hw0;
            lab0 = tgt32[(size_t)(tb + lane)       << shift];
            lab1 = tgt32[(size_t)(tb + lane +  32) << shift];
            lab2 = tgt32[(size_t)(tb + lane +  64) << shift];
            lab3 = tgt32[(size_t)(tb + lane +  96) << shift];
        }
    }

    bool first = true;
    while (true) {
        __syncthreads();
        const bool store = (t < NTILES);
        if (store) {
            if (tid < 512) {   // 4x STS.128, conflict-free
                float4* tr = (float4*)(tiles + par * TILE_F) + (q << 6) + slot;
                tr[0]  = make_float4(v0.x, v1.x, v2.x, v3.x);
                tr[16] = make_float4(v0.y, v1.y, v2.y, v3.y);
                tr[32] = make_float4(v0.z, v1.z, v2.z, v3.z);
                tr[48] = make_float4(v0.w, v1.w, v2.w, v3.w);
            } else if (wid == 19) {   // counting sort of 128 labels -> meta[par]
                int* bc = bcnt + par * 19;
                int* bs = bstart + par * 19;
                int* bu = bcur + par * 19;
                int* od = order + par * 128;
                int l0 = min(max(lab0, 0), 18), l1 = min(max(lab1, 0), 18);
                int l2 = min(max(lab2, 0), 18), l3 = min(max(lab3, 0), 18);
                if (lane < 19) bc[lane] = 0;
                __syncwarp();
                atomicAdd(&bc[l0], 1); atomicAdd(&bc[l1], 1);
                atomicAdd(&bc[l2], 1); atomicAdd(&bc[l3], 1);
                __syncwarp();
                int c = (lane < 19) ? bc[lane] : 0;
                int x = c;
                #pragma unroll
                for (int off = 1; off < 32; off <<= 1) {
                    int y = __shfl_up_sync(0xffffffffu, x, off);
                    if (lane >= off) x += y;
                }
                if (lane < 19) { bs[lane] = x - c; bu[lane] = x - c; }
                __syncwarp();
                int p0 = atomicAdd(&bu[l0], 1); od[p0] = lane;
                int p1 = atomicAdd(&bu[l1], 1); od[p1] = lane + 32;
                int p2 = atomicAdd(&bu[l2], 1); od[p2] = lane + 64;
                int p3 = atomicAdd(&bu[l3], 1); od[p3] = lane + 96;
            }
        }
        const int nt = t + GRID1;
        if (nt < NTILES) {   // prefetch next tile (latency spans full iteration)
            const int nb = nt >> 11, nh = (nt & 2047) << 7;
            if (tid < 512) {
                const float* p = inp + ((size_t)nb << 24) + nh + (q << 2);
                v0 = __ldcs((const float4*)(p + (size_t)c0 * HW));
                v1 = __ldcs((const float4*)(p + (size_t)c1 * HW));
                v2 = __ldcs((const float4*)(p + (size_t)c2 * HW));
                v3 = __ldcs((const float4*)(p + (size_t)c3 * HW));
            } else if (wid == 19) {
                const int tb = (nb << 18) + nh;
                lab0 = tgt32[(size_t)(tb + lane)       << shift];
                lab1 = tgt32[(size_t)(tb + lane +  32) << shift];
                lab2 = tgt32[(size_t)(tb + lane +  64) << shift];
                lab3 = tgt32[(size_t)(tb + lane +  96) << shift];
            }
        }
        // accumulate previous tile from buf[par^1]
        if (!first && wid < K) {
            const int pp   = par ^ 1;
            const int base = bstart[pp * 19 + wid];
            const int n    = bcnt[pp * 19 + wid];
            const int* od  = order + pp * 128;
            const float4* tb4 = (const float4*)(tiles + pp * TILE_F);
            ccnt += n;
            int i = 0;
            for (; i + 2 <= n; i += 2) {    // halves take entries i and i+1
                const int p = od[base + i + h];
                float4 f = tb4[(p << 4) + (g ^ ((p >> 2) & 15))];
                r0 += f.x; r1 += f.y; r2 += f.z; r3 += f.w;
            }
            if (i < n && h == 0) {          // odd tail: lanes 0-15 only
                const int p = od[base + i];
                float4 f = tb4[(p << 4) + (g ^ ((p >> 2) & 15))];
                r0 += f.x; r1 += f.y; r2 += f.z; r3 += f.w;
            }
        }
        first = false;
        if (!store) break;     // post-last iteration: final accumulate done
        t = nt; par ^= 1;
    }

    // ---- merge halves + write per-block partials ----
    if (wid < K) {
        r0 += __shfl_xor_sync(0xffffffffu, r0, 16);
        r1 += __shfl_xor_sync(0xffffffffu, r1, 16);
        r2 += __shfl_xor_sync(0xffffffffu, r2, 16);
        r3 += __shfl_xor_sync(0xffffffffu, r3, 16);
        if (lane < 16) {
            float* dst = g_psums + bid * KC + (wid << 6);
            dst[g]      = r0;
            dst[g + 16] = r1;
            dst[g + 32] = r2;
            dst[g + 48] = r3;
        }
        if (lane == 0) g_pcnts[wid * GRID1 + bid] = ccnt;
    }
}

// ---------------------------------------------------------------------------
// K2 (fused tail): 152 blocks x 256 threads reduce psums columns -> g_sums;
// last block (atomic ticket) computes counts + centroids + loss.
// ---------------------------------------------------------------------------
__global__ __launch_bounds__(256) void k2_kernel(float* __restrict__ out) {
    __shared__ float4 red[256];
    __shared__ unsigned ticket;
    const int tid = threadIdx.x;
    const int half = tid >> 7;                 // which of the 2 columns
    const int r    = tid & 127;                // row lane within column
    const int col  = (blockIdx.x << 1) + half; // 0..303
    const float4* ps = (const float4*)g_psums;
    float4 s = make_float4(0.f, 0.f, 0.f, 0.f);
    for (int row = r; row < GRID1; row += 128) {
        float4 v = ps[row * 304 + col];
        s.x += v.x; s.y += v.y; s.z += v.z; s.w += v.w;
    }
    red[tid] = s;
    __syncthreads();
    #pragma unroll
    for (int off = 64; off > 0; off >>= 1) {
        if (r < off) {
            float4 o = red[tid + off];
            s.x += o.x; s.y += o.y; s.z += o.z; s.w += o.w;
            red[tid] = s;
        }
        __syncthreads();
    }
    if (r == 0) ((float4*)g_sums)[col] = red[half << 7];

    // ---- last-block election ----
    __threadfence();
    if (tid == 0) ticket = atomicAdd(&g_done, 1);
    __syncthreads();
    if (ticket != 151) return;
    if (tid == 0) g_done = 0;                  // reset for next graph replay

    __shared__ float cen[KC];
    __shared__ float nrm[K];
    __shared__ int   cnts[K];
    __shared__ float red2[256];
    const int wid = tid >> 5, lane = tid & 31;

    // counts: 8 warps loop over classes, coalesced + shfl
    for (int cls = wid; cls < K; cls += 8) {
        int sc = 0;
        for (int p = lane; p < GRID1; p += 32) sc += g_pcnts[cls * GRID1 + p];
        #pragma unroll
        for (int off = 16; off > 0; off >>= 1) sc += __shfl_xor_sync(0xffffffffu, sc, off);
        if (lane == 0) cnts[cls] = sc;
    }
    __syncthreads();
    for (int i = tid; i < KC; i += 256)
        cen[i] = g_sums[i] / fmaxf((float)cnts[i >> 6], 1.0f);
    __syncthreads();
    if (tid < K) {
        float nn = 0.f;
        #pragma unroll
        for (int c = 0; c < 64; ++c) { float v = cen[(tid << 6) + c]; nn += v * v; }
        nrm[tid] = fmaxf(sqrtf(nn), 1e-8f);
    }
    __syncthreads();
    for (int i = tid; i < KC; i += 256)
        cen[i] = cen[i] / nrm[i >> 6];
    __syncthreads();

    float val = 0.f;
    for (int pair = tid; pair < K * K; pair += 256) {
        const int k1i = pair / K, k2i = pair % K;
        float dot = 0.f;
        #pragma unroll
        for (int c = 0; c < 64; ++c)
            dot += cen[(k1i << 6) + c] * cen[(k2i << 6) + c];
        val += (k1i == k2i) ? (1.0f - dot) : fmaxf(dot, 0.0f);
    }
    red2[tid] = val;
    __syncthreads();
    #pragma unroll
    for (int off = 128; off > 0; off >>= 1) {
        if (tid < off) red2[tid] += red2[tid + off];
        __syncthreads();
    }
    if (tid == 0) out[0] = red2[0] / 6859.0f;   // K^3
}

// ---------------------------------------------------------------------------
extern "C" void kernel_launch(void* const* d_in, const int* in_sizes, int n_in,
                              void* d_out, int out_size) {
    // Select pointers by element count (inputs: 134M, targets: 2M) — robust to order.
    int ii = 0, ti = 1;
    if (n_in >= 2 && in_sizes[1] > in_sizes[0]) { ii = 1; ti = 0; }
    const float* inp = (const float*)d_in[ii];
    const int* tgt32 = (const int*)d_in[ti];
    cudaFuncSetAttribute(k1_kernel, cudaFuncAttributeMaxDynamicSharedMemorySize, SMEM_BYTES);
    k1_kernel<<<GRID1, 640, SMEM_BYTES>>>(inp, tgt32);
    k2_kernel<<<152, 256>>>((float*)d_out);
}

// round 8
// speedup vs baseline: 1.1282x; 1.1282x over previous
#include <cuda_runtime.h>
#include <math.h>

// Problem constants
#define HW      262144        // 512*512
#define NTILES  16384         // 2M pixels / 128-pixel tiles
#define GRID1   296           // 2 * 148 SMs
#define K       19
#define KC      1216          // 19*64

// Scratch (no allocation allowed -> __device__ globals)
__device__ float g_psums[GRID1 * KC];
__device__ int   g_pcnts[K * GRID1];     // [class][block]
__device__ float g_sums[KC];
__device__ int   g_cnt[K];

#define TILE_F   8192
// dyn smem: 2 tiles + order[2][128] + bstart/bcnt/bcur[2][19]
#define SMEM_BYTES (2*TILE_F*4 + 2*128*4 + 3*2*19*4 + 64)

// ---------------------------------------------------------------------------
// K1: streaming centroid scatter-sum, class-owned register accumulation,
// double-buffered single-barrier pipeline. (R6 version verbatim — 87.3us,
// DRAM 79.3%; R7 float4 variant measured neutral, reverted.)
// ---------------------------------------------------------------------------
__global__ __launch_bounds__(640, 2) void k1_kernel(const float* __restrict__ inp,
                                                    const int* __restrict__ tgt32) {
    extern __shared__ float sm[];
    float* tiles  = sm;                        // [2][8192]
    int*   order  = (int*)(sm + 2 * TILE_F);   // [2][128]
    int*   bstart = order + 256;               // [2][19]
    int*   bcnt   = bstart + 38;               // [2][19]
    int*   bcur   = bcnt + 38;                 // [2][19]

    const int tid  = threadIdx.x;
    const int lane = tid & 31;
    const int wid  = tid >> 5;
    const int bid  = blockIdx.x;

    // loader mapping (tid < 512): q = pixel-quad, channel pairs (w,32+w),(16+w,48+w)
    const int q = tid & 31, w = (tid >> 5) & 15;
    const int c0 = w, c1 = 16 + w, c2 = 32 + w, c3 = 48 + w;
    const int slot0 = 2 * (w ^ q);
    const int slot1 = 2 * ((w ^ q) ^ 16);

    float a0 = 0.f, a1 = 0.f, b0 = 0.f, b1 = 0.f;
    int   ccnt = 0;
    float4 v0, v1, v2, v3;
    int   lab0 = 0, lab1 = 0, lab2 = 0, lab3 = 0;
    int   shift = 0;

    int t = bid, par = 0;

    // ---- prologue: prefetch tile bid (data + labels), detect targets dtype ----
    {
        const int b = t >> 11, hw0 = (t & 2047) << 7;
        if (tid < 512) {
            const float* p = inp + ((size_t)b << 24) + hw0 + (q << 2);
            v0 = __ldcs((const float4*)(p + (size_t)c0 * HW));
            v1 = __ldcs((const float4*)(p + (size_t)c1 * HW));
            v2 = __ldcs((const float4*)(p + (size_t)c2 * HW));
            v3 = __ldcs((const float4*)(p + (size_t)c3 * HW));
        }
        if (wid == 19) {
            // int64 labels 0..18 have all-zero high words; int32 ~never does
            if (lane == 0) {
                int all0 = 1;
                #pragma unroll
                for (int i = 0; i < 32; ++i)
                    if (tgt32[2 * i + 1] != 0) all0 = 0;
                shift = all0;
            }
            shift = __shfl_sync(0xffffffffu, shift, 0);
            const int tb = (b << 18) + hw0;
            lab0 = tgt32[(size_t)(tb + lane)       << shift];
            lab1 = tgt32[(size_t)(tb + lane +  32) << shift];
            lab2 = tgt32[(size_t)(tb + lane +  64) << shift];
            lab3 = tgt32[(size_t)(tb + lane +  96) << shift];
        }
    }

    bool first = true;
    while (true) {
        __syncthreads();
        const bool store = (t < NTILES);
        if (store) {
            if (tid < 512) {   // STS.64, conflict-free
                float* r = tiles + par * TILE_F + (q << 8);
                *(float2*)(r +       slot0) = make_float2(v0.x, v2.x);
                *(float2*)(r +  64 + slot0) = make_float2(v0.y, v2.y);
                *(float2*)(r + 128 + slot0) = make_float2(v0.z, v2.z);
                *(float2*)(r + 192 + slot0) = make_float2(v0.w, v2.w);
                *(float2*)(r +       slot1) = make_float2(v1.x, v3.x);
                *(float2*)(r +  64 + slot1) = make_float2(v1.y, v3.y);
                *(float2*)(r + 128 + slot1) = make_float2(v1.z, v3.z);
                *(float2*)(r + 192 + slot1) = make_float2(v1.w, v3.w);
            } else if (wid == 19) {   // counting sort of 128 labels -> meta[par]
                int* bc = bcnt + par * 19;
                int* bs = bstart + par * 19;
                int* bu = bcur + par * 19;
                int* od = order + par * 128;
                int l0 = min(max(lab0, 0), 18), l1 = min(max(lab1, 0), 18);
                int l2 = min(max(lab2, 0), 18), l3 = min(max(lab3, 0), 18);
                if (lane < 19) bc[lane] = 0;
                __syncwarp();
                atomicAdd(&bc[l0], 1); atomicAdd(&bc[l1], 1);
                atomicAdd(&bc[l2], 1); atomicAdd(&bc[l3], 1);
                __syncwarp();
                int c = (lane < 19) ? bc[lane] : 0;
                int x = c;
                #pragma unroll
                for (int off = 1; off < 32; off <<= 1) {
                    int y = __shfl_up_sync(0xffffffffu, x, off);
                    if (lane >= off) x += y;
                }
                if (lane < 19) { bs[lane] = x - c; bu[lane] = x - c; }
                __syncwarp();
                int p0 = atomicAdd(&bu[l0], 1); od[p0] = lane;
                int p1 = atomicAdd(&bu[l1], 1); od[p1] = lane + 32;
                int p2 = atomicAdd(&bu[l2], 1); od[p2] = lane + 64;
                int p3 = atomicAdd(&bu[l3], 1); od[p3] = lane + 96;
            }
        }
        const int nt = t + GRID1;
        if (nt < NTILES) {   // prefetch next tile (latency spans full iteration)
            const int nb = nt >> 11, nh = (nt & 2047) << 7;
            if (tid < 512) {
                const float* p = inp + ((size_t)nb << 24) + nh + (q << 2);
                v0 = __ldcs((const float4*)(p + (size_t)c0 * HW));
                v1 = __ldcs((const float4*)(p + (size_t)c1 * HW));
                v2 = __ldcs((const float4*)(p + (size_t)c2 * HW));
                v3 = __ldcs((const float4*)(p + (size_t)c3 * HW));
            } else if (wid == 19) {
                const int tb = (nb << 18) + nh;
                lab0 = tgt32[(size_t)(tb + lane)       << shift];
                lab1 = tgt32[(size_t)(tb + lane +  32) << shift];
                lab2 = tgt32[(size_t)(tb + lane +  64) << shift];
                lab3 = tgt32[(size_t)(tb + lane +  96) << shift];
            }
        }
        // accumulate previous tile from buf[par^1] (register accumulators)
        if (!first && wid < K) {
            const int pp   = par ^ 1;
            const int base = bstart[pp * 19 + wid];
            const int n    = bcnt[pp * 19 + wid];
            const int* od  = order + pp * 128;
            const float* tb = tiles + pp * TILE_F;
            ccnt += n;
            int i = 0;
            for (; i + 2 <= n; i += 2) {   // two independent chains
                const int pA = od[base + i], pB = od[base + i + 1];
                float2 fA = *(const float2*)(tb + (pA << 6) + 2 * (lane ^ ((pA >> 2) & 31)));
                float2 fB = *(const float2*)(tb + (pB << 6) + 2 * (lane ^ ((pB >> 2) & 31)));
                a0 += fA.x; a1 += fA.y;
                b0 += fB.x; b1 += fB.y;
            }
            if (i < n) {
                const int pA = od[base + i];
                float2 fA = *(const float2*)(tb + (pA << 6) + 2 * (lane ^ ((pA >> 2) & 31)));
                a0 += fA.x; a1 += fA.y;
            }
        }
        first = false;
        if (!store) break;     // post-last iteration: final accumulate done
        t = nt; par ^= 1;
    }

    // ---- write per-block partials ----
    if (wid < K) {
        g_psums[bid * KC + (wid << 6) + lane]      = a0 + b0;
        g_psums[bid * KC + (wid << 6) + 32 + lane] = a1 + b1;
        if (lane == 0) g_pcnts[wid * GRID1 + bid] = ccnt;
    }
}

// ---------------------------------------------------------------------------
// K2: wide psums reduce + counts. Blocks 0..151: 2 float4-columns each,
// 128 threads/column, coalesced rows + smem tree. Block 152: count reduce.
// ---------------------------------------------------------------------------
__global__ __launch_bounds__(256) void k2_kernel() {
    const int tid = threadIdx.x;
    if (blockIdx.x == 152) {      // counts: 8 warps over 19 classes
        const int wid = tid >> 5, lane = tid & 31;
        for (int cls = wid; cls < K; cls += 8) {
            int s = 0;
            for (int p = lane; p < GRID1; p += 32) s += g_pcnts[cls * GRID1 + p];
            #pragma unroll
            for (int off = 16; off > 0; off >>= 1) s += __shfl_xor_sync(0xffffffffu, s, off);
            if (lane == 0) g_cnt[cls] = s;
        }
        return;
    }
    __shared__ float4 red[256];
    const int half = tid >> 7;                 // which of the 2 columns
    const int r    = tid & 127;                // row lane within column
    const int col  = (blockIdx.x << 1) + half; // 0..303
    const float4* ps = (const float4*)g_psums;
    float4 s = make_float4(0.f, 0.f, 0.f, 0.f);
    for (int row = r; row < GRID1; row += 128) {
        float4 v = ps[row * 304 + col];
        s.x += v.x; s.y += v.y; s.z += v.z; s.w += v.w;
    }
    red[tid] = s;
    __syncthreads();
    #pragma unroll
    for (int off = 64; off > 0; off >>= 1) {
        if (r < off) {
            float4 o = red[tid + off];
            s.x += o.x; s.y += o.y; s.z += o.z; s.w += o.w;
            red[tid] = s;
        }
        __syncthreads();
    }
    if (r == 0) ((float4*)g_sums)[col] = red[half << 7];
}

// ---------------------------------------------------------------------------
// K3: centroids + norms (warp-per-class) + cosine-embedding loss. 1 block.
// ---------------------------------------------------------------------------
__global__ __launch_bounds__(640) void k3_kernel(float* __restrict__ out) {
    __shared__ float cen[KC];
    __shared__ float nrm[K];
    __shared__ int   cnts[K];
    __shared__ float red[512];
    const int tid = threadIdx.x;
    const int wid = tid >> 5, lane = tid & 31;

    if (tid < K) cnts[tid] = g_cnt[tid];
    __syncthreads();
    if (tid < 304) {   // float4 load + centroid divide (16 float4 per class)
        float inv = 1.0f / fmaxf((float)cnts[tid >> 4], 1.0f);
        float4 v = ((const float4*)g_sums)[tid];
        ((float4*)cen)[tid] = make_float4(v.x * inv, v.y * inv, v.z * inv, v.w * inv);
    }
    __syncthreads();
    if (wid < K) {     // warp per class: 2 elems/lane + shfl tree
        float x0 = cen[(wid << 6) + lane], x1 = cen[(wid << 6) + 32 + lane];
        float nn = x0 * x0 + x1 * x1;
        #pragma unroll
        for (int off = 16; off > 0; off >>= 1) nn += __shfl_xor_sync(0xffffffffu, nn, off);
        if (lane == 0) nrm[wid] = fmaxf(sqrtf(nn), 1e-8f);
    }
    __syncthreads();
    if (tid < 304) {
        float inv = 1.0f / nrm[tid >> 4];
        float4 v = ((const float4*)cen)[tid];
        ((float4*)cen)[tid] = make_float4(v.x * inv, v.y * inv, v.z * inv, v.w * inv);
    }
    __syncthreads();

    float val = 0.f;
    if (tid < K * K) {
        const int k1i = tid / K, k2i = tid % K;
        float dot = 0.f;
        #pragma unroll
        for (int c = 0; c < 64; ++c)
            dot += cen[(k1i << 6) + c] * cen[(k2i << 6) + c];
        val = (k1i == k2i) ? (1.0f - dot) : fmaxf(dot, 0.0f);
    }
    if (tid < 512) red[tid] = val;
    __syncthreads();
    #pragma unroll
    for (int off = 256; off > 0; off >>= 1) {
        if (tid < off) red[tid] += red[tid + off];
        __syncthreads();
    }
    if (tid == 0) out[0] = red[0] / 6859.0f;   // K^3
}

// ---------------------------------------------------------------------------
extern "C" void kernel_launch(void* const* d_in, const int* in_sizes, int n_in,
                              void* d_out, int out_size) {
    // Select pointers by element count (inputs: 134M, targets: 2M) — robust to order.
    int ii = 0, ti = 1;
    if (n_in >= 2 && in_sizes[1] > in_sizes[0]) { ii = 1; ti = 0; }
    const float* inp = (const float*)d_in[ii];
    const int* tgt32 = (const int*)d_in[ti];
    cudaFuncSetAttribute(k1_kernel, cudaFuncAttributeMaxDynamicSharedMemorySize, SMEM_BYTES);
    k1_kernel<<<GRID1, 640, SMEM_BYTES>>>(inp, tgt32);
    k2_kernel<<<153, 256>>>();
    k3_kernel<<<1, 640>>>((float*)d_out);
}